// round 2
// baseline (speedup 1.0000x reference)
#include <cuda_runtime.h>

// ---------------- problem constants ----------------
#define B_    2
#define T_    2048
#define C_    1024
#define NH    16
#define NKV   8
#define HD    64
#define E_    8
#define H_    2048
#define NTOK  (B_*T_)        // 4096
#define TOPK  2
#define CAP   2048           // 2*NTOK*TOPK/E_
#define EPSF  1.1920928955078125e-07f

// ---------------- scratch (device globals; no runtime alloc) ----------------
__device__ float g_xn [NTOK*C_];
__device__ float g_q  [NTOK*NH*HD];
__device__ float g_k  [NTOK*NKV*HD];
__device__ float g_v  [NTOK*NKV*HD];
__device__ float g_y  [NTOK*C_];
__device__ float g_x1 [NTOK*C_];
__device__ float g_xn2[NTOK*C_];
__device__ float g_h  [E_*CAP*H_];   // 33.5M floats
__device__ float g_bo [E_*CAP*C_];   // 16.8M floats
__device__ int   g_tke[NTOK*TOPK];
__device__ float g_tkw[NTOK*TOPK];
__device__ int   g_rowsrc[E_*CAP];
__device__ int   g_entryrow[NTOK*TOPK];
__device__ int   g_me[E_];

// ---------------- RMS norm (row-wise, 1024 cols) ----------------
__global__ __launch_bounds__(256) void rms_kernel(const float* __restrict__ x,
                                                  float* __restrict__ o) {
    int row = blockIdx.x;
    const float4* xr = (const float4*)(x + (long)row*C_);
    float4 v = xr[threadIdx.x];
    float ss = v.x*v.x + v.y*v.y + v.z*v.z + v.w*v.w;
    #pragma unroll
    for (int off = 16; off; off >>= 1) ss += __shfl_xor_sync(0xffffffffu, ss, off);
    __shared__ float sred[8];
    if ((threadIdx.x & 31) == 0) sred[threadIdx.x >> 5] = ss;
    __syncthreads();
    if (threadIdx.x == 0) {
        float t = 0.f;
        #pragma unroll
        for (int i = 0; i < 8; i++) t += sred[i];
        sred[0] = rsqrtf(t / (float)C_ + EPSF);
    }
    __syncthreads();
    float s = sred[0];
    v.x *= s; v.y *= s; v.z *= s; v.w *= s;
    ((float4*)(o + (long)row*C_))[threadIdx.x] = v;
}

// ---------------- generic NT GEMM: C[m,n] = sum_k A[m,k]*B[n,k] ----------------
// epi: 0 = none, 1 = C = Res + acc, 2 = C = relu(acc)^2
// rowsrc (nullable): A-row gather per expert z; mcounts (nullable): per-z M
#define BM 64
#define BN 64
#define BKK 16
__global__ __launch_bounds__(256) void gemm_nt(
    const float* __restrict__ A, long sA,
    const float* __restrict__ B, long sB,
    float* __restrict__ Cc, long sC,
    const float* __restrict__ Res,
    int M, int N, int K,
    const int* __restrict__ rowsrc, const int* __restrict__ mcounts,
    int cap, int epi)
{
    int e  = blockIdx.z;
    int Mz = mcounts ? mcounts[e] : M;
    int m0 = blockIdx.y * BM;
    if (m0 >= Mz) return;
    int n0 = blockIdx.x * BN;

    const float* Ab = A + (long)e * sA;
    const float* Bb = B + (long)e * sB;
    float*       Cb = Cc + (long)e * sC;
    const int*   rs = rowsrc ? (rowsrc + e * cap) : (const int*)0;

    __shared__ float As[BKK][BM + 1];
    __shared__ float Bs[BKK][BN + 1];

    int tid = threadIdx.x;
    int tx = tid & 15, ty = tid >> 4;

    long aoff[4]; bool av[4]; long boff[4];
    #pragma unroll
    for (int i = 0; i < 4; i++) {
        int m  = ty + 16 * i;
        int rm = m0 + m;
        av[i]  = (rm < Mz);
        int grow = av[i] ? (rs ? rs[rm] : rm) : 0;
        aoff[i] = (long)grow * K;
        boff[i] = (long)(n0 + m) * K;
    }

    float acc[4][4] = {};
    for (int k0 = 0; k0 < K; k0 += BKK) {
        #pragma unroll
        for (int i = 0; i < 4; i++) {
            As[tx][ty + 16*i] = av[i] ? Ab[aoff[i] + k0 + tx] : 0.f;
            Bs[tx][ty + 16*i] = Bb[boff[i] + k0 + tx];
        }
        __syncthreads();
        #pragma unroll
        for (int kk = 0; kk < BKK; kk++) {
            float a[4], b[4];
            #pragma unroll
            for (int j = 0; j < 4; j++) { a[j] = As[kk][ty*4 + j]; b[j] = Bs[kk][tx*4 + j]; }
            #pragma unroll
            for (int i = 0; i < 4; i++)
                #pragma unroll
                for (int j = 0; j < 4; j++)
                    acc[i][j] = fmaf(a[i], b[j], acc[i][j]);
        }
        __syncthreads();
    }

    #pragma unroll
    for (int i = 0; i < 4; i++) {
        int rm = m0 + ty*4 + i;
        if (rm >= Mz) continue;
        #pragma unroll
        for (int j = 0; j < 4; j++) {
            int col = n0 + tx*4 + j;
            float vv = acc[i][j];
            if (epi == 1)       vv += Res[(long)rm * N + col];
            else if (epi == 2) { vv = vv > 0.f ? vv : 0.f; vv = vv * vv; }
            Cb[(long)rm * N + col] = vv;
        }
    }
}

// ---------------- gate + v-update + RoPE + q/k RMS (per token) ----------------
__global__ __launch_bounds__(256) void gate_rope_kernel(
    const float* __restrict__ ve, const float* __restrict__ cosb,
    const float* __restrict__ sinb, const float* __restrict__ gw)
{
    int n = blockIdx.x;
    int tid = threadIdx.x, lane = tid & 31, w = tid >> 5;
    __shared__ float gs[8];
    float gsum = g_xn[(long)n*C_ + lane] * gw[w*32 + lane];
    #pragma unroll
    for (int off = 16; off; off >>= 1) gsum += __shfl_xor_sync(0xffffffffu, gsum, off);
    if (lane == 0) gs[w] = 2.f / (1.f + __expf(-gsum));
    __syncthreads();
    for (int idx = tid; idx < NKV*HD; idx += 256) {
        int kvh = idx >> 6;
        g_v[(long)n*(NKV*HD) + idx] += gs[kvh] * ve[(long)n*(NKV*HD) + idx];
    }
    int ts = n & (T_ - 1);
    float c = cosb[ts*32 + lane], s = sinb[ts*32 + lane];
    #pragma unroll
    for (int hh = 0; hh < 3; hh++) {
        float* p;
        if (hh == 0)      p = g_q + (long)n*(NH*HD)  + w*HD;
        else if (hh == 1) p = g_q + (long)n*(NH*HD)  + (w+8)*HD;
        else              p = g_k + (long)n*(NKV*HD) + w*HD;
        float x1 = p[lane], x2 = p[lane + 32];
        float o1 = x1*c + x2*s;
        float o2 = x2*c - x1*s;
        float ss = o1*o1 + o2*o2;
        #pragma unroll
        for (int off = 16; off; off >>= 1) ss += __shfl_xor_sync(0xffffffffu, ss, off);
        ss = __shfl_sync(0xffffffffu, ss, 0);
        float r = rsqrtf(ss / (float)HD + EPSF);
        p[lane]      = o1 * r;
        p[lane + 32] = o2 * r;
    }
}

// ---------------- sliding-window GQA attention ----------------
// grid (T/128, NH, B); block 128; thread-per-query flash with smem K/V tiles
__global__ __launch_bounds__(128) void attn_kernel(const int* __restrict__ wptr) {
    int W = wptr[0];
    int b = blockIdx.z, h = blockIdx.y;
    int qi  = blockIdx.x * 128 + threadIdx.x;
    int tok = b * T_ + qi;
    int kvh = h >> 1;  // rep = NH/NKV = 2

    const float* qp = g_q + (long)tok*(NH*HD) + h*HD;
    float qr[HD];
    #pragma unroll
    for (int i = 0; i < 16; i++) {
        float4 t4 = ((const float4*)qp)[i];
        qr[4*i+0] = t4.x * 0.125f; qr[4*i+1] = t4.y * 0.125f;
        qr[4*i+2] = t4.z * 0.125f; qr[4*i+3] = t4.w * 0.125f;
    }
    float acc[HD];
    #pragma unroll
    for (int d = 0; d < HD; d++) acc[d] = 0.f;
    float mi = -1e30f, li = 0.f;

    __shared__ float Ks[32][HD];
    __shared__ float Vs[32][HD];
    __shared__ float Ss[128][33];

    int qb   = blockIdx.x * 128;
    int jblo = qb - W; if (jblo < 0) jblo = 0;
    jblo &= ~31;
    int jbhi = qb + 127;
    int myjlo = qi - W; if (myjlo < 0) myjlo = 0;

    for (int j0 = jblo; j0 <= jbhi; j0 += 32) {
        #pragma unroll
        for (int i = 0; i < 4; i++) {
            int idx = threadIdx.x + i*128;
            int r = idx >> 4, c4 = idx & 15;
            long off = (long)(b*T_ + j0 + r) * (NKV*HD) + kvh*HD + c4*4;
            ((float4*)&Ks[r][0])[c4] = *(const float4*)(g_k + off);
            ((float4*)&Vs[r][0])[c4] = *(const float4*)(g_v + off);
        }
        __syncthreads();
        int lo = j0 > myjlo ? j0 : myjlo;
        int hi = (j0 + 31) < qi ? (j0 + 31) : qi;
        if (lo <= hi) {
            float mloc = -1e30f;
            for (int j = lo; j <= hi; j++) {
                const float4* kr = (const float4*)&Ks[j - j0][0];
                float s = 0.f;
                #pragma unroll
                for (int d4 = 0; d4 < 16; d4++) {
                    float4 kv = kr[d4];
                    s = fmaf(qr[4*d4+0], kv.x, s);
                    s = fmaf(qr[4*d4+1], kv.y, s);
                    s = fmaf(qr[4*d4+2], kv.z, s);
                    s = fmaf(qr[4*d4+3], kv.w, s);
                }
                Ss[threadIdx.x][j - j0] = s;
                mloc = s > mloc ? s : mloc;
            }
            float mnew = mi > mloc ? mi : mloc;
            float corr = __expf(mi - mnew);
            li *= corr;
            #pragma unroll
            for (int d = 0; d < HD; d++) acc[d] *= corr;
            for (int j = lo; j <= hi; j++) {
                float p = __expf(Ss[threadIdx.x][j - j0] - mnew);
                li += p;
                const float4* vr = (const float4*)&Vs[j - j0][0];
                #pragma unroll
                for (int d4 = 0; d4 < 16; d4++) {
                    float4 vv = vr[d4];
                    acc[4*d4+0] = fmaf(p, vv.x, acc[4*d4+0]);
                    acc[4*d4+1] = fmaf(p, vv.y, acc[4*d4+1]);
                    acc[4*d4+2] = fmaf(p, vv.z, acc[4*d4+2]);
                    acc[4*d4+3] = fmaf(p, vv.w, acc[4*d4+3]);
                }
            }
            mi = mnew;
        }
        __syncthreads();
    }
    float inv = 1.f / li;
    float* yp = g_y + (long)tok*C_ + h*HD;
    #pragma unroll
    for (int i = 0; i < 16; i++) {
        float4 o4;
        o4.x = acc[4*i+0]*inv; o4.y = acc[4*i+1]*inv;
        o4.z = acc[4*i+2]*inv; o4.w = acc[4*i+3]*inv;
        ((float4*)yp)[i] = o4;
    }
}

// ---------------- router: softmax over 8 experts + top-2 ----------------
__global__ __launch_bounds__(256) void router_kernel(const float* __restrict__ rww,
                                                     float* __restrict__ out_rw) {
    int n = blockIdx.x;
    int lane = threadIdx.x & 31, w = threadIdx.x >> 5;
    const float* xr = g_xn2 + (long)n*C_;
    const float* wr = rww + (long)w*C_;
    float sum = 0.f;
    for (int kk = lane; kk < C_; kk += 32) sum = fmaf(xr[kk], wr[kk], sum);
    #pragma unroll
    for (int off = 16; off; off >>= 1) sum += __shfl_xor_sync(0xffffffffu, sum, off);
    __shared__ float lg[8];
    if (lane == 0) lg[w] = sum;
    __syncthreads();
    if (threadIdx.x == 0) {
        float mx = lg[0];
        #pragma unroll
        for (int e = 1; e < 8; e++) mx = lg[e] > mx ? lg[e] : mx;
        float ex[8], s = 0.f;
        #pragma unroll
        for (int e = 0; e < 8; e++) { ex[e] = __expf(lg[e] - mx); s += ex[e]; }
        float inv = 1.f / s;
        float rw[8];
        #pragma unroll
        for (int e = 0; e < 8; e++) { rw[e] = ex[e] * inv; out_rw[(long)n*E_ + e] = rw[e]; }
        int i0 = 0;
        #pragma unroll
        for (int e = 1; e < 8; e++) if (rw[e] > rw[i0]) i0 = e;
        int i1 = (i0 == 0) ? 1 : 0;
        #pragma unroll
        for (int e = 0; e < 8; e++) if (e != i0 && rw[e] > rw[i1]) i1 = e;
        float w0 = rw[i0], w1 = rw[i1];
        float d = w0 + w1 + 1e-10f;
        g_tke[2*n]   = i0; g_tke[2*n+1] = i1;
        g_tkw[2*n]   = w0 / d; g_tkw[2*n+1] = w1 / d;
    }
}

// ---------------- stable expert dispatch (single block) ----------------
__global__ __launch_bounds__(256) void route_kernel() {
    __shared__ int cnts[256][8];
    int tid = threadIdx.x;
    int c[8]; 
    #pragma unroll
    for (int e = 0; e < 8; e++) c[e] = 0;
    int base = tid * 32;
    for (int i = 0; i < 32; i++) c[g_tke[base + i]]++;
    #pragma unroll
    for (int e = 0; e < 8; e++) cnts[tid][e] = c[e];
    __syncthreads();
    if (tid < 8) {
        int run = 0;
        for (int t = 0; t < 256; t++) { int tmp = cnts[t][tid]; cnts[t][tid] = run; run += tmp; }
        g_me[tid] = run < CAP ? run : CAP;
    }
    __syncthreads();
    #pragma unroll
    for (int e = 0; e < 8; e++) c[e] = cnts[tid][e];
    for (int i = 0; i < 32; i++) {
        int gi = base + i;
        int e = g_tke[gi];
        int pos = c[e]++;
        if (pos < CAP) {
            int row = e * CAP + pos;
            g_rowsrc[row]   = gi >> 1;   // token id
            g_entryrow[gi]  = row;
        } else {
            g_entryrow[gi] = -1;
        }
    }
}

// ---------------- combine: x_out = x1 + sum_slots w * bo[row] ----------------
__global__ __launch_bounds__(256) void combine_kernel(float* __restrict__ outx) {
    int n = blockIdx.x, tid = threadIdx.x;
    float4 r = ((const float4*)(g_x1 + (long)n*C_))[tid];
    #pragma unroll
    for (int s = 0; s < 2; s++) {
        int row = g_entryrow[n*2 + s];
        if (row >= 0) {
            float ww = g_tkw[n*2 + s];
            float4 bv = ((const float4*)(g_bo + (long)row*C_))[tid];
            r.x = fmaf(ww, bv.x, r.x); r.y = fmaf(ww, bv.y, r.y);
            r.z = fmaf(ww, bv.z, r.z); r.w = fmaf(ww, bv.w, r.w);
        }
    }
    ((float4*)(outx + (long)n*C_))[tid] = r;
}

// ---------------- host launcher ----------------
extern "C" void kernel_launch(void* const* d_in, const int* in_sizes, int n_in,
                              void* d_out, int out_size) {
    const float* x    = (const float*)d_in[0];
    const float* ve   = (const float*)d_in[1];
    const float* cosb = (const float*)d_in[2];
    const float* sinb = (const float*)d_in[3];
    const float* cqw  = (const float*)d_in[4];
    const float* ckw  = (const float*)d_in[5];
    const float* cvw  = (const float*)d_in[6];
    const float* cpw  = (const float*)d_in[7];
    const float* gw   = (const float*)d_in[8];
    const float* rww  = (const float*)d_in[9];
    const float* fcw  = (const float*)d_in[10];
    const float* pjw  = (const float*)d_in[11];
    const int*   wptr = (const int*)d_in[12];
    float* out = (float*)d_out;

    float *xn, *q, *k, *v, *y, *x1, *xn2, *h, *bo;
    int *rowsrc, *me;
    cudaGetSymbolAddress((void**)&xn,  g_xn);
    cudaGetSymbolAddress((void**)&q,   g_q);
    cudaGetSymbolAddress((void**)&k,   g_k);
    cudaGetSymbolAddress((void**)&v,   g_v);
    cudaGetSymbolAddress((void**)&y,   g_y);
    cudaGetSymbolAddress((void**)&x1,  g_x1);
    cudaGetSymbolAddress((void**)&xn2, g_xn2);
    cudaGetSymbolAddress((void**)&h,   g_h);
    cudaGetSymbolAddress((void**)&bo,  g_bo);
    cudaGetSymbolAddress((void**)&rowsrc, g_rowsrc);
    cudaGetSymbolAddress((void**)&me,     g_me);

    // 1) xn = rms(x)
    rms_kernel<<<NTOK, 256>>>(x, xn);
    // 2) q/k/v projections
    gemm_nt<<<dim3(NH*HD/64,  NTOK/64, 1), 256>>>(xn, 0, cqw, 0, q, 0, nullptr,
                                                  NTOK, NH*HD,  C_, nullptr, nullptr, 0, 0);
    gemm_nt<<<dim3(NKV*HD/64, NTOK/64, 1), 256>>>(xn, 0, ckw, 0, k, 0, nullptr,
                                                  NTOK, NKV*HD, C_, nullptr, nullptr, 0, 0);
    gemm_nt<<<dim3(NKV*HD/64, NTOK/64, 1), 256>>>(xn, 0, cvw, 0, v, 0, nullptr,
                                                  NTOK, NKV*HD, C_, nullptr, nullptr, 0, 0);
    // 3) gate + v update + rope + q/k rms
    gate_rope_kernel<<<NTOK, 256>>>(ve, cosb, sinb, gw);
    // 4) attention
    attn_kernel<<<dim3(T_/128, NH, B_), 128>>>(wptr);
    // 5) x1 = x + y @ c_proj^T
    gemm_nt<<<dim3(C_/64, NTOK/64, 1), 256>>>(y, 0, cpw, 0, x1, 0, x,
                                              NTOK, C_, C_, nullptr, nullptr, 0, 1);
    // 6) xn2 = rms(x1)
    rms_kernel<<<NTOK, 256>>>(x1, xn2);
    // 7) router softmax + top-2 (writes rw output region)
    router_kernel<<<NTOK, 256>>>(rww, out + (long)NTOK * C_);
    // 8) stable dispatch
    route_kernel<<<1, 256>>>();
    // 9) h = relu(xn2[gather] @ fc_w[e]^T)^2   (only valid rows)
    gemm_nt<<<dim3(H_/64, CAP/64, E_), 256>>>(xn2, 0, fcw, (long)H_*C_,
                                              h, (long)CAP*H_, nullptr,
                                              CAP, H_, C_, rowsrc, me, CAP, 2);
    // 10) bo = h @ proj_w[e]^T
    gemm_nt<<<dim3(C_/64, CAP/64, E_), 256>>>(h, (long)CAP*H_, pjw, (long)C_*H_,
                                              bo, (long)CAP*C_, nullptr,
                                              CAP, C_, H_, nullptr, me, CAP, 0);
    // 11) final combine -> x output region
    combine_kernel<<<NTOK, 256>>>(out);
}

// round 7
// speedup vs baseline: 2.7416x; 2.7416x over previous
#include <cuda_runtime.h>

// ---------------- problem constants ----------------
#define B_    2
#define T_    2048
#define C_    1024
#define NH    16
#define NKV   8
#define HD    64
#define E_    8
#define H_    2048
#define NTOK  (B_*T_)        // 4096
#define TOPK  2
#define CAP   2048           // 2*NTOK*TOPK/E_
#define EPSF  1.1920928955078125e-07f

// ---------------- scratch (device globals; no runtime alloc) ----------------
__device__ float g_xn [NTOK*C_];
__device__ float g_q  [NTOK*NH*HD];
__device__ float g_k  [NTOK*NKV*HD];
__device__ float g_v  [NTOK*NKV*HD];
__device__ float g_y  [NTOK*C_];
__device__ float g_x1 [NTOK*C_];
__device__ float g_xn2[NTOK*C_];
__device__ float g_h  [E_*CAP*H_];
__device__ float g_bo [E_*CAP*C_];
__device__ int   g_tke[NTOK*TOPK];
__device__ float g_tkw[NTOK*TOPK];
__device__ int   g_rowsrc[E_*CAP];
__device__ int   g_entryrow[NTOK*TOPK];
__device__ int   g_me[E_];

// ---------------- RMS norm ----------------
__global__ __launch_bounds__(256) void rms_kernel(const float* __restrict__ x,
                                                  float* __restrict__ o) {
    int row = blockIdx.x;
    const float4* xr = (const float4*)(x + (long)row*C_);
    float4 v = xr[threadIdx.x];
    float ss = v.x*v.x + v.y*v.y + v.z*v.z + v.w*v.w;
    #pragma unroll
    for (int off = 16; off; off >>= 1) ss += __shfl_xor_sync(0xffffffffu, ss, off);
    __shared__ float sred[8];
    if ((threadIdx.x & 31) == 0) sred[threadIdx.x >> 5] = ss;
    __syncthreads();
    if (threadIdx.x == 0) {
        float t = 0.f;
        #pragma unroll
        for (int i = 0; i < 8; i++) t += sred[i];
        sred[0] = rsqrtf(t / (float)C_ + EPSF);
    }
    __syncthreads();
    float s = sred[0];
    v.x *= s; v.y *= s; v.z *= s; v.w *= s;
    ((float4*)(o + (long)row*C_))[threadIdx.x] = v;
}

// ---------------- bf16x2 split-precision tensor-core NT GEMM ----------------
// C[m,n] = sum_k A[m,k] * B[n,k]
// epi: 0 none, 1 C=Res+acc, 2 C=relu(acc)^2
// Split each fp32 into hi=bf16_rn(x), lo=bf16_rn(x-hi); compute
// hi*hi + hi*lo + lo*hi (drop lo*lo ~ 2^-18, sign-incoherent).
__device__ __forceinline__ void split2(float f0, float f1, unsigned &hi, unsigned &lo) {
    unsigned h;
    asm("cvt.rn.bf16x2.f32 %0, %1, %2;" : "=r"(h) : "f"(f1), "f"(f0));
    float h0 = __uint_as_float(h << 16);
    float h1 = __uint_as_float(h & 0xffff0000u);
    float r0 = f0 - h0;
    float r1 = f1 - h1;
    unsigned l;
    asm("cvt.rn.bf16x2.f32 %0, %1, %2;" : "=r"(l) : "f"(r1), "f"(r0));
    hi = h; lo = l;
}
__device__ __forceinline__ void mma_bf16(float* c, const unsigned* a, const unsigned* b) {
    asm volatile(
        "mma.sync.aligned.m16n8k16.row.col.f32.bf16.bf16.f32 "
        "{%0,%1,%2,%3},{%4,%5,%6,%7},{%8,%9},{%0,%1,%2,%3};"
        : "+f"(c[0]), "+f"(c[1]), "+f"(c[2]), "+f"(c[3])
        : "r"(a[0]), "r"(a[1]), "r"(a[2]), "r"(a[3]), "r"(b[0]), "r"(b[1]));
}
// swizzled smem index (row-major [rows][32] floats, kvec xor row&7)
__device__ __forceinline__ int sidx(int r, int k) {
    return r*32 + ((((k>>2) ^ (r&7)))<<2) + (k&3);
}

template<int BN>
__global__ void __launch_bounds__(256, 1) gemm_tc(
    const float* __restrict__ A, long sA,
    const float* __restrict__ Bw, long sB,
    float* __restrict__ Cc, long sC,
    const float* __restrict__ Res,
    int M, int N, int K,
    const int* __restrict__ rowsrc, const int* __restrict__ mcounts,
    int epi)
{
    constexpr int BM = 128, BK = 32;
    constexpr int WN = BN/4;       // warp n-extent
    constexpr int NT = WN/8;       // n-tiles per warp
    constexpr int BROWS = BN/32;   // B cp.async rows per thread

    int e  = blockIdx.z;
    int Mz = mcounts ? mcounts[e] : M;
    int m0 = blockIdx.y * BM;
    if (m0 >= Mz) return;
    int n0 = blockIdx.x * BN;

    const float* Ab = A + (long)e * sA;
    const float* Bb = Bw + (long)e * sB;
    float*       Cb = Cc + (long)e * sC;

    extern __shared__ float smem[];
    float* As = smem;                 // [2][BM*BK]
    float* Bs = smem + 2*BM*BK;       // [2][BN*BK]

    int tid = threadIdx.x;
    int kq    = tid & 7;              // 16B chunk within 32-float row
    int rbase = tid >> 3;             // 0..31

    const float* arow[4]; int adst[4];
    #pragma unroll
    for (int i = 0; i < 4; i++) {
        int r  = rbase + 32*i;
        int gm = m0 + r; if (gm >= Mz) gm = Mz - 1;
        int grow = rowsrc ? rowsrc[e*CAP + gm] : gm;
        arow[i] = Ab + (long)grow*K + kq*4;
        adst[i] = r*BK + ((kq ^ (r&7))<<2);
    }
    const float* brow[BROWS]; int bdst[BROWS];
    #pragma unroll
    for (int i = 0; i < BROWS; i++) {
        int r = rbase + 32*i;
        brow[i] = Bb + (long)(n0 + r)*K + kq*4;
        bdst[i] = r*BK + ((kq ^ (r&7))<<2);
    }

    unsigned sAb = (unsigned)__cvta_generic_to_shared(As);
    unsigned sBb = (unsigned)__cvta_generic_to_shared(Bs);

    int wid = tid >> 5, lane = tid & 31;
    int wm = wid >> 2, wn = wid & 3;
    int g = lane >> 2, tig = lane & 3;

    float acc[4][NT][4];
    #pragma unroll
    for (int i = 0; i < 4; i++)
        #pragma unroll
        for (int j = 0; j < NT; j++)
            #pragma unroll
            for (int q = 0; q < 4; q++) acc[i][j][q] = 0.f;

    auto load_tile = [&](int stage, int k0) {
        unsigned ao = sAb + (unsigned)(stage*BM*BK)*4u;
        unsigned bo = sBb + (unsigned)(stage*BN*BK)*4u;
        #pragma unroll
        for (int i = 0; i < 4; i++)
            asm volatile("cp.async.cg.shared.global [%0], [%1], 16;"
                         :: "r"(ao + (unsigned)adst[i]*4u), "l"(arow[i] + k0));
        #pragma unroll
        for (int i = 0; i < BROWS; i++)
            asm volatile("cp.async.cg.shared.global [%0], [%1], 16;"
                         :: "r"(bo + (unsigned)bdst[i]*4u), "l"(brow[i] + k0));
        asm volatile("cp.async.commit_group;");
    };

    auto compute = [&](int stage) {
        const float* Ap = As + stage*BM*BK;
        const float* Bp = Bs + stage*BN*BK;
        #pragma unroll
        for (int kc = 0; kc < 2; kc++) {           // two k16 chunks per BK=32
            int klo = kc*16 + 2*tig;
            int khi = klo + 8;
            unsigned bhi[NT][2], blo[NT][2];
            #pragma unroll
            for (int j = 0; j < NT; j++) {
                int rn_ = wn*WN + j*8 + g;
                split2(Bp[sidx(rn_, klo)], Bp[sidx(rn_, klo+1)], bhi[j][0], blo[j][0]);
                split2(Bp[sidx(rn_, khi)], Bp[sidx(rn_, khi+1)], bhi[j][1], blo[j][1]);
            }
            #pragma unroll
            for (int i = 0; i < 4; i++) {
                int r0 = wm*64 + i*16 + g;
                unsigned ahi[4], alo[4];
                split2(Ap[sidx(r0,   klo)], Ap[sidx(r0,   klo+1)], ahi[0], alo[0]);
                split2(Ap[sidx(r0+8, klo)], Ap[sidx(r0+8, klo+1)], ahi[1], alo[1]);
                split2(Ap[sidx(r0,   khi)], Ap[sidx(r0,   khi+1)], ahi[2], alo[2]);
                split2(Ap[sidx(r0+8, khi)], Ap[sidx(r0+8, khi+1)], ahi[3], alo[3]);
                #pragma unroll
                for (int j = 0; j < NT; j++) {
                    mma_bf16(acc[i][j], ahi, bhi[j]);
                    mma_bf16(acc[i][j], ahi, blo[j]);
                    mma_bf16(acc[i][j], alo, bhi[j]);
                }
            }
        }
    };

    int KT = K / BK;
    load_tile(0, 0);
    for (int kt = 0; kt < KT; kt++) {
        if (kt + 1 < KT) {
            load_tile((kt + 1) & 1, (kt + 1)*BK);
            asm volatile("cp.async.wait_group 1;");
        } else {
            asm volatile("cp.async.wait_group 0;");
        }
        __syncthreads();
        compute(kt & 1);
        __syncthreads();
    }

    // epilogue (m16n8k16 C layout == m16n8k8 C layout)
    #pragma unroll
    for (int i = 0; i < 4; i++) {
        int rm0 = m0 + wm*64 + i*16 + g;
        #pragma unroll
        for (int half = 0; half < 2; half++) {
            int rm = rm0 + half*8;
            if (rm < Mz) {
                #pragma unroll
                for (int j = 0; j < NT; j++) {
                    int col = n0 + wn*WN + j*8 + tig*2;
                    float v0 = acc[i][j][half*2 + 0];
                    float v1 = acc[i][j][half*2 + 1];
                    if (epi == 1) {
                        float2 rr = *(const float2*)&Res[(long)rm*N + col];
                        v0 += rr.x; v1 += rr.y;
                    } else if (epi == 2) {
                        v0 = fmaxf(v0, 0.f); v0 *= v0;
                        v1 = fmaxf(v1, 0.f); v1 *= v1;
                    }
                    *(float2*)&Cb[(long)rm*N + col] = make_float2(v0, v1);
                }
            }
        }
    }
}

// ---------------- gate + v-update + RoPE + q/k RMS ----------------
__global__ __launch_bounds__(256) void gate_rope_kernel(
    const float* __restrict__ ve, const float* __restrict__ cosb,
    const float* __restrict__ sinb, const float* __restrict__ gw)
{
    int n = blockIdx.x;
    int tid = threadIdx.x, lane = tid & 31, w = tid >> 5;
    __shared__ float gs[8];
    float gsum = g_xn[(long)n*C_ + lane] * gw[w*32 + lane];
    #pragma unroll
    for (int off = 16; off; off >>= 1) gsum += __shfl_xor_sync(0xffffffffu, gsum, off);
    if (lane == 0) gs[w] = 2.f / (1.f + __expf(-gsum));
    __syncthreads();
    for (int idx = tid; idx < NKV*HD; idx += 256) {
        int kvh = idx >> 6;
        g_v[(long)n*(NKV*HD) + idx] += gs[kvh] * ve[(long)n*(NKV*HD) + idx];
    }
    int ts = n & (T_ - 1);
    float c = cosb[ts*32 + lane], s = sinb[ts*32 + lane];
    #pragma unroll
    for (int hh = 0; hh < 3; hh++) {
        float* p;
        if (hh == 0)      p = g_q + (long)n*(NH*HD)  + w*HD;
        else if (hh == 1) p = g_q + (long)n*(NH*HD)  + (w+8)*HD;
        else              p = g_k + (long)n*(NKV*HD) + w*HD;
        float x1 = p[lane], x2 = p[lane + 32];
        float o1 = x1*c + x2*s;
        float o2 = x2*c - x1*s;
        float ss = o1*o1 + o2*o2;
        #pragma unroll
        for (int off = 16; off; off >>= 1) ss += __shfl_xor_sync(0xffffffffu, ss, off);
        ss = __shfl_sync(0xffffffffu, ss, 0);
        float r = rsqrtf(ss / (float)HD + EPSF);
        p[lane]      = o1 * r;
        p[lane + 32] = o2 * r;
    }
}

// ---------------- sliding-window GQA attention ----------------
__global__ __launch_bounds__(128) void attn_kernel(const int* __restrict__ wptr) {
    int W = wptr[0];
    int b = blockIdx.z, h = blockIdx.y;
    int qi  = blockIdx.x * 128 + threadIdx.x;
    int tok = b * T_ + qi;
    int kvh = h >> 1;

    const float* qp = g_q + (long)tok*(NH*HD) + h*HD;
    float qr[HD];
    #pragma unroll
    for (int i = 0; i < 16; i++) {
        float4 t4 = ((const float4*)qp)[i];
        qr[4*i+0] = t4.x * 0.125f; qr[4*i+1] = t4.y * 0.125f;
        qr[4*i+2] = t4.z * 0.125f; qr[4*i+3] = t4.w * 0.125f;
    }
    float acc[HD];
    #pragma unroll
    for (int d = 0; d < HD; d++) acc[d] = 0.f;
    float mi = -1e30f, li = 0.f;

    __shared__ float Ks[32][HD];
    __shared__ float Vs[32][HD];
    __shared__ float Ss[128][33];

    int qb   = blockIdx.x * 128;
    int jblo = qb - W; if (jblo < 0) jblo = 0;
    jblo &= ~31;
    int jbhi = qb + 127;
    int myjlo = qi - W; if (myjlo < 0) myjlo = 0;

    for (int j0 = jblo; j0 <= jbhi; j0 += 32) {
        #pragma unroll
        for (int i = 0; i < 4; i++) {
            int idx = threadIdx.x + i*128;
            int r = idx >> 4, c4 = idx & 15;
            long off = (long)(b*T_ + j0 + r) * (NKV*HD) + kvh*HD + c4*4;
            ((float4*)&Ks[r][0])[c4] = *(const float4*)(g_k + off);
            ((float4*)&Vs[r][0])[c4] = *(const float4*)(g_v + off);
        }
        __syncthreads();
        int lo = j0 > myjlo ? j0 : myjlo;
        int hi = (j0 + 31) < qi ? (j0 + 31) : qi;
        if (lo <= hi) {
            float mloc = -1e30f;
            for (int j = lo; j <= hi; j++) {
                const float4* kr = (const float4*)&Ks[j - j0][0];
                float s = 0.f;
                #pragma unroll
                for (int d4 = 0; d4 < 16; d4++) {
                    float4 kv = kr[d4];
                    s = fmaf(qr[4*d4+0], kv.x, s);
                    s = fmaf(qr[4*d4+1], kv.y, s);
                    s = fmaf(qr[4*d4+2], kv.z, s);
                    s = fmaf(qr[4*d4+3], kv.w, s);
                }
                Ss[threadIdx.x][j - j0] = s;
                mloc = s > mloc ? s : mloc;
            }
            float mnew = mi > mloc ? mi : mloc;
            float corr = __expf(mi - mnew);
            li *= corr;
            #pragma unroll
            for (int d = 0; d < HD; d++) acc[d] *= corr;
            for (int j = lo; j <= hi; j++) {
                float p = __expf(Ss[threadIdx.x][j - j0] - mnew);
                li += p;
                const float4* vr = (const float4*)&Vs[j - j0][0];
                #pragma unroll
                for (int d4 = 0; d4 < 16; d4++) {
                    float4 vv = vr[d4];
                    acc[4*d4+0] = fmaf(p, vv.x, acc[4*d4+0]);
                    acc[4*d4+1] = fmaf(p, vv.y, acc[4*d4+1]);
                    acc[4*d4+2] = fmaf(p, vv.z, acc[4*d4+2]);
                    acc[4*d4+3] = fmaf(p, vv.w, acc[4*d4+3]);
                }
            }
            mi = mnew;
        }
        __syncthreads();
    }
    float inv = 1.f / li;
    float* yp = g_y + (long)tok*C_ + h*HD;
    #pragma unroll
    for (int i = 0; i < 16; i++) {
        float4 o4;
        o4.x = acc[4*i+0]*inv; o4.y = acc[4*i+1]*inv;
        o4.z = acc[4*i+2]*inv; o4.w = acc[4*i+3]*inv;
        ((float4*)yp)[i] = o4;
    }
}

// ---------------- router: softmax over 8 experts + top-2 ----------------
__global__ __launch_bounds__(256) void router_kernel(const float* __restrict__ rww,
                                                     float* __restrict__ out_rw) {
    int n = blockIdx.x;
    int lane = threadIdx.x & 31, w = threadIdx.x >> 5;
    const float* xr = g_xn2 + (long)n*C_;
    const float* wr = rww + (long)w*C_;
    float sum = 0.f;
    for (int kk = lane; kk < C_; kk += 32) sum = fmaf(xr[kk], wr[kk], sum);
    #pragma unroll
    for (int off = 16; off; off >>= 1) sum += __shfl_xor_sync(0xffffffffu, sum, off);
    __shared__ float lg[8];
    if (lane == 0) lg[w] = sum;
    __syncthreads();
    if (threadIdx.x == 0) {
        float mx = lg[0];
        #pragma unroll
        for (int e = 1; e < 8; e++) mx = lg[e] > mx ? lg[e] : mx;
        float ex[8], s = 0.f;
        #pragma unroll
        for (int e = 0; e < 8; e++) { ex[e] = __expf(lg[e] - mx); s += ex[e]; }
        float inv = 1.f / s;
        float rw[8];
        #pragma unroll
        for (int e = 0; e < 8; e++) { rw[e] = ex[e] * inv; out_rw[(long)n*E_ + e] = rw[e]; }
        int i0 = 0;
        #pragma unroll
        for (int e = 1; e < 8; e++) if (rw[e] > rw[i0]) i0 = e;
        int i1 = (i0 == 0) ? 1 : 0;
        #pragma unroll
        for (int e = 0; e < 8; e++) if (e != i0 && rw[e] > rw[i1]) i1 = e;
        float w0 = rw[i0], w1 = rw[i1];
        float d = w0 + w1 + 1e-10f;
        g_tke[2*n]   = i0; g_tke[2*n+1] = i1;
        g_tkw[2*n]   = w0 / d; g_tkw[2*n+1] = w1 / d;
    }
}

// ---------------- stable expert dispatch (single block) ----------------
__global__ __launch_bounds__(256) void route_kernel() {
    __shared__ int cnts[256][8];
    int tid = threadIdx.x;
    int c[8];
    #pragma unroll
    for (int e = 0; e < 8; e++) c[e] = 0;
    int base = tid * 32;
    for (int i = 0; i < 32; i++) c[g_tke[base + i]]++;
    #pragma unroll
    for (int e = 0; e < 8; e++) cnts[tid][e] = c[e];
    __syncthreads();
    if (tid < 8) {
        int run = 0;
        for (int t = 0; t < 256; t++) { int tmp = cnts[t][tid]; cnts[t][tid] = run; run += tmp; }
        g_me[tid] = run < CAP ? run : CAP;
    }
    __syncthreads();
    #pragma unroll
    for (int e = 0; e < 8; e++) c[e] = cnts[tid][e];
    for (int i = 0; i < 32; i++) {
        int gi = base + i;
        int e = g_tke[gi];
        int pos = c[e]++;
        if (pos < CAP) {
            int row = e * CAP + pos;
            g_rowsrc[row]   = gi >> 1;
            g_entryrow[gi]  = row;
        } else {
            g_entryrow[gi] = -1;
        }
    }
}

// ---------------- combine ----------------
__global__ __launch_bounds__(256) void combine_kernel(float* __restrict__ outx) {
    int n = blockIdx.x, tid = threadIdx.x;
    float4 r = ((const float4*)(g_x1 + (long)n*C_))[tid];
    #pragma unroll
    for (int s = 0; s < 2; s++) {
        int row = g_entryrow[n*2 + s];
        if (row >= 0) {
            float ww = g_tkw[n*2 + s];
            float4 bv = ((const float4*)(g_bo + (long)row*C_))[tid];
            r.x = fmaf(ww, bv.x, r.x); r.y = fmaf(ww, bv.y, r.y);
            r.z = fmaf(ww, bv.z, r.z); r.w = fmaf(ww, bv.w, r.w);
        }
    }
    ((float4*)(outx + (long)n*C_))[tid] = r;
}

// ---------------- host launcher ----------------
extern "C" void kernel_launch(void* const* d_in, const int* in_sizes, int n_in,
                              void* d_out, int out_size) {
    const float* x    = (const float*)d_in[0];
    const float* ve   = (const float*)d_in[1];
    const float* cosb = (const float*)d_in[2];
    const float* sinb = (const float*)d_in[3];
    const float* cqw  = (const float*)d_in[4];
    const float* ckw  = (const float*)d_in[5];
    const float* cvw  = (const float*)d_in[6];
    const float* cpw  = (const float*)d_in[7];
    const float* gw   = (const float*)d_in[8];
    const float* rww  = (const float*)d_in[9];
    const float* fcw  = (const float*)d_in[10];
    const float* pjw  = (const float*)d_in[11];
    const int*   wptr = (const int*)d_in[12];
    float* out = (float*)d_out;

    float *xn, *q, *k, *v, *y, *x1, *xn2, *h, *bo;
    int *rowsrc, *me;
    cudaGetSymbolAddress((void**)&xn,  g_xn);
    cudaGetSymbolAddress((void**)&q,   g_q);
    cudaGetSymbolAddress((void**)&k,   g_k);
    cudaGetSymbolAddress((void**)&v,   g_v);
    cudaGetSymbolAddress((void**)&y,   g_y);
    cudaGetSymbolAddress((void**)&x1,  g_x1);
    cudaGetSymbolAddress((void**)&xn2, g_xn2);
    cudaGetSymbolAddress((void**)&h,   g_h);
    cudaGetSymbolAddress((void**)&bo,  g_bo);
    cudaGetSymbolAddress((void**)&rowsrc, g_rowsrc);
    cudaGetSymbolAddress((void**)&me,     g_me);

    const int SMEM128 = 2*(128*32 + 128*32)*4;   // 65536
    const int SMEM256 = 2*(128*32 + 256*32)*4;   // 98304
    cudaFuncSetAttribute(gemm_tc<128>, cudaFuncAttributeMaxDynamicSharedMemorySize, SMEM128);
    cudaFuncSetAttribute(gemm_tc<256>, cudaFuncAttributeMaxDynamicSharedMemorySize, SMEM256);

    // 1) xn = rms(x)
    rms_kernel<<<NTOK, 256>>>(x, xn);
    // 2) q/k/v projections (tensor cores, bf16x2 split)
    gemm_tc<256><<<dim3(NH*HD/256,  NTOK/128, 1), 256, SMEM256>>>(
        xn, 0, cqw, 0, q, 0, nullptr, NTOK, NH*HD,  C_, nullptr, nullptr, 0);
    gemm_tc<128><<<dim3(NKV*HD/128, NTOK/128, 1), 256, SMEM128>>>(
        xn, 0, ckw, 0, k, 0, nullptr, NTOK, NKV*HD, C_, nullptr, nullptr, 0);
    gemm_tc<128><<<dim3(NKV*HD/128, NTOK/128, 1), 256, SMEM128>>>(
        xn, 0, cvw, 0, v, 0, nullptr, NTOK, NKV*HD, C_, nullptr, nullptr, 0);
    // 3) gate + v update + rope + q/k rms
    gate_rope_kernel<<<NTOK, 256>>>(ve, cosb, sinb, gw);
    // 4) attention
    attn_kernel<<<dim3(T_/128, NH, B_), 128>>>(wptr);
    // 5) x1 = x + y @ c_proj^T
    gemm_tc<256><<<dim3(C_/256, NTOK/128, 1), 256, SMEM256>>>(
        y, 0, cpw, 0, x1, 0, x, NTOK, C_, C_, nullptr, nullptr, 1);
    // 6) xn2 = rms(x1)
    rms_kernel<<<NTOK, 256>>>(x1, xn2);
    // 7) router softmax + top-2 (fp32 exact; writes rw output region)
    router_kernel<<<NTOK, 256>>>(rww, out + (long)NTOK * C_);
    // 8) stable dispatch
    route_kernel<<<1, 256>>>();
    // 9) h = relu(xn2[gather] @ fc_w[e]^T)^2
    gemm_tc<256><<<dim3(H_/256, CAP/128, E_), 256, SMEM256>>>(
        xn2, 0, fcw, (long)H_*C_, h, (long)CAP*H_, nullptr,
        CAP, H_, C_, rowsrc, me, 2);
    // 10) bo = h @ proj_w[e]^T
    gemm_tc<256><<<dim3(C_/256, CAP/128, E_), 256, SMEM256>>>(
        h, (long)CAP*H_, pjw, (long)C_*H_, bo, (long)CAP*C_, nullptr,
        CAP, C_, H_, nullptr, me, 0);
    // 11) final combine -> x output region
    combine_kernel<<<NTOK, 256>>>(out);
}

// round 9
// speedup vs baseline: 2.8572x; 1.0422x over previous
#include <cuda_runtime.h>

// ---------------- problem constants ----------------
#define B_    2
#define T_    2048
#define C_    1024
#define NH    16
#define NKV   8
#define HD    64
#define E_    8
#define H_    2048
#define NTOK  (B_*T_)        // 4096
#define TOPK  2
#define CAP   2048           // 2*NTOK*TOPK/E_
#define EPSF  1.1920928955078125e-07f

// ---------------- scratch (device globals; no runtime alloc) ----------------
__device__ float g_xn [NTOK*C_];
__device__ float g_q  [NTOK*NH*HD];
__device__ float g_k  [NTOK*NKV*HD];
__device__ float g_v  [NTOK*NKV*HD];
__device__ float g_y  [NTOK*C_];
__device__ float g_x1 [NTOK*C_];
__device__ float g_xn2[NTOK*C_];
__device__ float g_bo [E_*CAP*C_];
__device__ int   g_tke[NTOK*TOPK];
__device__ float g_tkw[NTOK*TOPK];
__device__ int   g_rowsrc[E_*CAP];
__device__ int   g_entryrow[NTOK*TOPK];
__device__ int   g_me[E_];

// bf16 hi/lo split buffers
__device__ unsigned short s_xn_h [NTOK*C_],      s_xn_l [NTOK*C_];
__device__ unsigned short s_y_h  [NTOK*C_],      s_y_l  [NTOK*C_];
__device__ unsigned short s_xn2_h[NTOK*C_],      s_xn2_l[NTOK*C_];
__device__ unsigned short w_q_h [NH*HD*C_],      w_q_l [NH*HD*C_];
__device__ unsigned short w_k_h [NKV*HD*C_],     w_k_l [NKV*HD*C_];
__device__ unsigned short w_v_h [NKV*HD*C_],     w_v_l [NKV*HD*C_];
__device__ unsigned short w_p_h [C_*C_],         w_p_l [C_*C_];
__device__ unsigned short w_fc_h[E_*H_*C_],      w_fc_l[E_*H_*C_];
__device__ unsigned short w_pj_h[E_*C_*H_],      w_pj_l[E_*C_*H_];
__device__ unsigned short s_h_h [E_*CAP*H_],     s_h_l [E_*CAP*H_];

// ---------------- helpers ----------------
__device__ __forceinline__ void split2(float f0, float f1, unsigned &hi, unsigned &lo) {
    unsigned h;
    asm("cvt.rn.bf16x2.f32 %0, %1, %2;" : "=r"(h) : "f"(f1), "f"(f0));
    float h0 = __uint_as_float(h << 16);
    float h1 = __uint_as_float(h & 0xffff0000u);
    float r0 = f0 - h0;
    float r1 = f1 - h1;
    unsigned l;
    asm("cvt.rn.bf16x2.f32 %0, %1, %2;" : "=r"(l) : "f"(r1), "f"(r0));
    hi = h; lo = l;
}
__device__ __forceinline__ void mma_bf16(float* c, const unsigned* a, const unsigned* b) {
    asm volatile(
        "mma.sync.aligned.m16n8k16.row.col.f32.bf16.bf16.f32 "
        "{%0,%1,%2,%3},{%4,%5,%6,%7},{%8,%9},{%0,%1,%2,%3};"
        : "+f"(c[0]), "+f"(c[1]), "+f"(c[2]), "+f"(c[3])
        : "r"(a[0]), "r"(a[1]), "r"(a[2]), "r"(a[3]), "r"(b[0]), "r"(b[1]));
}
__device__ __forceinline__ void ldsm4(unsigned &r0, unsigned &r1, unsigned &r2, unsigned &r3,
                                      unsigned addr) {
    asm volatile("ldmatrix.sync.aligned.m8n8.x4.shared.b16 {%0,%1,%2,%3}, [%4];"
                 : "=r"(r0), "=r"(r1), "=r"(r2), "=r"(r3) : "r"(addr));
}

// ---------------- split: f32 -> bf16 hi/lo ----------------
__global__ __launch_bounds__(256) void split_kernel(const float* __restrict__ in,
                                                    unsigned* __restrict__ hi,
                                                    unsigned* __restrict__ lo, int n2) {
    int i = blockIdx.x*256 + threadIdx.x;
    if (i < n2) {
        float2 f = ((const float2*)in)[i];
        unsigned h, l;
        split2(f.x, f.y, h, l);
        hi[i] = h; lo[i] = l;
    }
}

// ---------------- RMS norm ----------------
__global__ __launch_bounds__(256) void rms_kernel(const float* __restrict__ x,
                                                  float* __restrict__ o) {
    int row = blockIdx.x;
    const float4* xr = (const float4*)(x + (long)row*C_);
    float4 v = xr[threadIdx.x];
    float ss = v.x*v.x + v.y*v.y + v.z*v.z + v.w*v.w;
    #pragma unroll
    for (int off = 16; off; off >>= 1) ss += __shfl_xor_sync(0xffffffffu, ss, off);
    __shared__ float sred[8];
    if ((threadIdx.x & 31) == 0) sred[threadIdx.x >> 5] = ss;
    __syncthreads();
    if (threadIdx.x == 0) {
        float t = 0.f;
        #pragma unroll
        for (int i = 0; i < 8; i++) t += sred[i];
        sred[0] = rsqrtf(t / (float)C_ + EPSF);
    }
    __syncthreads();
    float s = sred[0];
    v.x *= s; v.y *= s; v.z *= s; v.w *= s;
    ((float4*)(o + (long)row*C_))[threadIdx.x] = v;
}

// ---------------- bf16 hi/lo split-precision tensor GEMM ----------------
// C[m,n] = sum_k A[m,k]*B[n,k], split product hi*hi + hi*lo + lo*hi
// epi: 0 fp32 out, 1 fp32 out + Res, 2 relu(acc)^2 -> split bf16 out (Chi/Clo)
// BM=128, BN=128, BK=32, 256 threads, 3-stage cp.async, ldmatrix fragments.
__global__ __launch_bounds__(256) void gemm_bf(
    const unsigned short* __restrict__ Ah, const unsigned short* __restrict__ Al, long sA,
    const unsigned short* __restrict__ Bh, const unsigned short* __restrict__ Bl, long sB,
    float* __restrict__ Cf, unsigned* __restrict__ Chi, unsigned* __restrict__ Clo, long sC,
    const float* __restrict__ Res,
    int M, int N, int K,
    const int* __restrict__ rowsrc, const int* __restrict__ mcounts, int epi)
{
    constexpr int BK = 32;
    int e  = blockIdx.z;
    int Mz = mcounts ? mcounts[e] : M;
    int m0 = blockIdx.y * 128;
    if (m0 >= Mz) return;
    int n0 = blockIdx.x * 128;

    const unsigned short* Ahb = Ah + (long)e * sA;
    const unsigned short* Alb = Al + (long)e * sA;
    const unsigned short* Bhb = Bh + (long)e * sB;
    const unsigned short* Blb = Bl + (long)e * sB;

    extern __shared__ unsigned short sm[];
    unsigned sbase = (unsigned)__cvta_generic_to_shared(sm);
    // stage layout (bytes): [Ahi 8K][Alo 8K][Bhi 8K][Blo 8K] = 32KB/stage, 3 stages

    int tid = threadIdx.x;
    int lr = tid >> 2, lc = tid & 3;     // loader: row lr & lr+64, 16B chunk lc

    long aoff[2], boff[2]; int sdst[2];
    #pragma unroll
    for (int t = 0; t < 2; t++) {
        int r  = lr + 64*t;
        int gm = m0 + r; if (gm >= Mz) gm = Mz - 1;
        int grow = rowsrc ? rowsrc[e*CAP + gm] : gm;
        aoff[t] = (long)grow*K + lc*8;
        boff[t] = (long)(n0 + r)*K + lc*8;
        sdst[t] = r*64 + ((lc ^ ((r>>1)&3)) << 4);
    }

    auto load_tile = [&](int stage, int k0) {
        unsigned sb = sbase + stage*32768u;
        #pragma unroll
        for (int t = 0; t < 2; t++) {
            asm volatile("cp.async.cg.shared.global [%0], [%1], 16;"
                         :: "r"(sb + sdst[t]),          "l"(Ahb + aoff[t] + k0));
            asm volatile("cp.async.cg.shared.global [%0], [%1], 16;"
                         :: "r"(sb + 8192u + sdst[t]),  "l"(Alb + aoff[t] + k0));
            asm volatile("cp.async.cg.shared.global [%0], [%1], 16;"
                         :: "r"(sb + 16384u + sdst[t]), "l"(Bhb + boff[t] + k0));
            asm volatile("cp.async.cg.shared.global [%0], [%1], 16;"
                         :: "r"(sb + 24576u + sdst[t]), "l"(Blb + boff[t] + k0));
        }
        asm volatile("cp.async.commit_group;");
    };

    int wid = tid >> 5, lane = tid & 31;
    int wm = wid >> 2, wn = wid & 3;     // 2 x 4 warps, warp tile 64m x 32n
    int g = lane >> 2, tig = lane & 3;

    // per-lane ldmatrix row bases
    int rA[4], rAx[4];
    #pragma unroll
    for (int i = 0; i < 4; i++) { rA[i] = wm*64 + i*16 + (lane & 15); rAx[i] = (rA[i]>>1)&3; }
    int chA = lane >> 4;                  // k-half for A
    int rB[2], rBx[2];
    #pragma unroll
    for (int jp = 0; jp < 2; jp++) {
        rB[jp]  = wn*32 + jp*16 + 8*(lane>>4) + (lane & 7);
        rBx[jp] = (rB[jp]>>1)&3;
    }
    int chB = (lane >> 3) & 1;            // k-half for B

    float acc[4][4][4];
    #pragma unroll
    for (int i = 0; i < 4; i++)
        #pragma unroll
        for (int j = 0; j < 4; j++)
            #pragma unroll
            for (int q = 0; q < 4; q++) acc[i][j][q] = 0.f;

    auto compute = [&](int stage) {
        unsigned sb = sbase + stage*32768u;
        #pragma unroll
        for (int kc = 0; kc < 2; kc++) {
            unsigned bh[4][2], bl[4][2];
            #pragma unroll
            for (int jp = 0; jp < 2; jp++) {
                unsigned addr = sb + 16384u + (unsigned)(rB[jp]*64 + (((kc*2 + chB) ^ rBx[jp]) << 4));
                ldsm4(bh[2*jp][0], bh[2*jp][1], bh[2*jp+1][0], bh[2*jp+1][1], addr);
                ldsm4(bl[2*jp][0], bl[2*jp][1], bl[2*jp+1][0], bl[2*jp+1][1], addr + 8192u);
            }
            #pragma unroll
            for (int i = 0; i < 4; i++) {
                unsigned addrA = sb + (unsigned)(rA[i]*64 + (((kc*2 + chA) ^ rAx[i]) << 4));
                unsigned ah[4], al[4];
                ldsm4(ah[0], ah[1], ah[2], ah[3], addrA);
                ldsm4(al[0], al[1], al[2], al[3], addrA + 8192u);
                #pragma unroll
                for (int j = 0; j < 4; j++) {
                    mma_bf16(acc[i][j], ah, bh[j]);
                    mma_bf16(acc[i][j], ah, bl[j]);
                    mma_bf16(acc[i][j], al, bh[j]);
                }
            }
        }
    };

    int KT = K / BK;
    load_tile(0, 0);
    load_tile(1, BK);
    for (int kt = 0; kt < KT; kt++) {
        if (kt + 2 < KT) {
            load_tile((kt + 2) % 3, (kt + 2)*BK);
            asm volatile("cp.async.wait_group 2;");
        } else {
            asm volatile("cp.async.wait_group 0;");
        }
        __syncthreads();
        compute(kt % 3);
        __syncthreads();
    }

    // epilogue
    #pragma unroll
    for (int i = 0; i < 4; i++) {
        int rm0 = m0 + wm*64 + i*16 + g;
        #pragma unroll
        for (int half = 0; half < 2; half++) {
            int rm = rm0 + half*8;
            if (rm < Mz) {
                #pragma unroll
                for (int j = 0; j < 4; j++) {
                    int col = n0 + wn*32 + j*8 + tig*2;
                    float v0 = acc[i][j][half*2 + 0];
                    float v1 = acc[i][j][half*2 + 1];
                    if (epi == 1) {
                        float2 rr = *(const float2*)&Res[(long)rm*N + col];
                        v0 += rr.x; v1 += rr.y;
                        *(float2*)&Cf[(long)e*sC + (long)rm*N + col] = make_float2(v0, v1);
                    } else if (epi == 2) {
                        v0 = fmaxf(v0, 0.f); v0 *= v0;
                        v1 = fmaxf(v1, 0.f); v1 *= v1;
                        unsigned h, l;
                        split2(v0, v1, h, l);
                        long idx = ((long)e*sC + (long)rm*N + col) >> 1;
                        Chi[idx] = h; Clo[idx] = l;
                    } else {
                        *(float2*)&Cf[(long)e*sC + (long)rm*N + col] = make_float2(v0, v1);
                    }
                }
            }
        }
    }
}

// ---------------- gate + v-update + RoPE + q/k RMS ----------------
__global__ __launch_bounds__(256) void gate_rope_kernel(
    const float* __restrict__ ve, const float* __restrict__ cosb,
    const float* __restrict__ sinb, const float* __restrict__ gw)
{
    int n = blockIdx.x;
    int tid = threadIdx.x, lane = tid & 31, w = tid >> 5;
    __shared__ float gs[8];
    float gsum = g_xn[(long)n*C_ + lane] * gw[w*32 + lane];
    #pragma unroll
    for (int off = 16; off; off >>= 1) gsum += __shfl_xor_sync(0xffffffffu, gsum, off);
    if (lane == 0) gs[w] = 2.f / (1.f + __expf(-gsum));
    __syncthreads();
    for (int idx = tid; idx < NKV*HD; idx += 256) {
        int kvh = idx >> 6;
        g_v[(long)n*(NKV*HD) + idx] += gs[kvh] * ve[(long)n*(NKV*HD) + idx];
    }
    int ts = n & (T_ - 1);
    float c = cosb[ts*32 + lane], s = sinb[ts*32 + lane];
    #pragma unroll
    for (int hh = 0; hh < 3; hh++) {
        float* p;
        if (hh == 0)      p = g_q + (long)n*(NH*HD)  + w*HD;
        else if (hh == 1) p = g_q + (long)n*(NH*HD)  + (w+8)*HD;
        else              p = g_k + (long)n*(NKV*HD) + w*HD;
        float x1 = p[lane], x2 = p[lane + 32];
        float o1 = x1*c + x2*s;
        float o2 = x2*c - x1*s;
        float ss = o1*o1 + o2*o2;
        #pragma unroll
        for (int off = 16; off; off >>= 1) ss += __shfl_xor_sync(0xffffffffu, ss, off);
        ss = __shfl_sync(0xffffffffu, ss, 0);
        float r = rsqrtf(ss / (float)HD + EPSF);
        p[lane]      = o1 * r;
        p[lane + 32] = o2 * r;
    }
}

// ---------------- sliding-window GQA attention ----------------
__global__ __launch_bounds__(128) void attn_kernel(const int* __restrict__ wptr) {
    int W = wptr[0];
    int b = blockIdx.z, h = blockIdx.y;
    int qi  = blockIdx.x * 128 + threadIdx.x;
    int tok = b * T_ + qi;
    int kvh = h >> 1;

    const float* qp = g_q + (long)tok*(NH*HD) + h*HD;
    float qr[HD];
    #pragma unroll
    for (int i = 0; i < 16; i++) {
        float4 t4 = ((const float4*)qp)[i];
        qr[4*i+0] = t4.x * 0.125f; qr[4*i+1] = t4.y * 0.125f;
        qr[4*i+2] = t4.z * 0.125f; qr[4*i+3] = t4.w * 0.125f;
    }
    float acc[HD];
    #pragma unroll
    for (int d = 0; d < HD; d++) acc[d] = 0.f;
    float mi = -1e30f, li = 0.f;

    __shared__ float Ks[32][HD];
    __shared__ float Vs[32][HD];
    __shared__ float Ss[128][33];

    int qb   = blockIdx.x * 128;
    int jblo = qb - W; if (jblo < 0) jblo = 0;
    jblo &= ~31;
    int jbhi = qb + 127;
    int myjlo = qi - W; if (myjlo < 0) myjlo = 0;

    for (int j0 = jblo; j0 <= jbhi; j0 += 32) {
        #pragma unroll
        for (int i = 0; i < 4; i++) {
            int idx = threadIdx.x + i*128;
            int r = idx >> 4, c4 = idx & 15;
            long off = (long)(b*T_ + j0 + r) * (NKV*HD) + kvh*HD + c4*4;
            ((float4*)&Ks[r][0])[c4] = *(const float4*)(g_k + off);
            ((float4*)&Vs[r][0])[c4] = *(const float4*)(g_v + off);
        }
        __syncthreads();
        int lo = j0 > myjlo ? j0 : myjlo;
        int hi = (j0 + 31) < qi ? (j0 + 31) : qi;
        if (lo <= hi) {
            float mloc = -1e30f;
            for (int j = lo; j <= hi; j++) {
                const float4* kr = (const float4*)&Ks[j - j0][0];
                float s = 0.f;
                #pragma unroll
                for (int d4 = 0; d4 < 16; d4++) {
                    float4 kv = kr[d4];
                    s = fmaf(qr[4*d4+0], kv.x, s);
                    s = fmaf(qr[4*d4+1], kv.y, s);
                    s = fmaf(qr[4*d4+2], kv.z, s);
                    s = fmaf(qr[4*d4+3], kv.w, s);
                }
                Ss[threadIdx.x][j - j0] = s;
                mloc = s > mloc ? s : mloc;
            }
            float mnew = mi > mloc ? mi : mloc;
            float corr = __expf(mi - mnew);
            li *= corr;
            #pragma unroll
            for (int d = 0; d < HD; d++) acc[d] *= corr;
            for (int j = lo; j <= hi; j++) {
                float p = __expf(Ss[threadIdx.x][j - j0] - mnew);
                li += p;
                const float4* vr = (const float4*)&Vs[j - j0][0];
                #pragma unroll
                for (int d4 = 0; d4 < 16; d4++) {
                    float4 vv = vr[d4];
                    acc[4*d4+0] = fmaf(p, vv.x, acc[4*d4+0]);
                    acc[4*d4+1] = fmaf(p, vv.y, acc[4*d4+1]);
                    acc[4*d4+2] = fmaf(p, vv.z, acc[4*d4+2]);
                    acc[4*d4+3] = fmaf(p, vv.w, acc[4*d4+3]);
                }
            }
            mi = mnew;
        }
        __syncthreads();
    }
    float inv = 1.f / li;
    float* yp = g_y + (long)tok*C_ + h*HD;
    #pragma unroll
    for (int i = 0; i < 16; i++) {
        float4 o4;
        o4.x = acc[4*i+0]*inv; o4.y = acc[4*i+1]*inv;
        o4.z = acc[4*i+2]*inv; o4.w = acc[4*i+3]*inv;
        ((float4*)yp)[i] = o4;
    }
}

// ---------------- router: softmax over 8 experts + top-2 ----------------
__global__ __launch_bounds__(256) void router_kernel(const float* __restrict__ rww,
                                                     float* __restrict__ out_rw) {
    int n = blockIdx.x;
    int lane = threadIdx.x & 31, w = threadIdx.x >> 5;
    const float* xr = g_xn2 + (long)n*C_;
    const float* wr = rww + (long)w*C_;
    float sum = 0.f;
    for (int kk = lane; kk < C_; kk += 32) sum = fmaf(xr[kk], wr[kk], sum);
    #pragma unroll
    for (int off = 16; off; off >>= 1) sum += __shfl_xor_sync(0xffffffffu, sum, off);
    __shared__ float lg[8];
    if (lane == 0) lg[w] = sum;
    __syncthreads();
    if (threadIdx.x == 0) {
        float mx = lg[0];
        #pragma unroll
        for (int e = 1; e < 8; e++) mx = lg[e] > mx ? lg[e] : mx;
        float ex[8], s = 0.f;
        #pragma unroll
        for (int e = 0; e < 8; e++) { ex[e] = __expf(lg[e] - mx); s += ex[e]; }
        float inv = 1.f / s;
        float rw[8];
        #pragma unroll
        for (int e = 0; e < 8; e++) { rw[e] = ex[e] * inv; out_rw[(long)n*E_ + e] = rw[e]; }
        int i0 = 0;
        #pragma unroll
        for (int e = 1; e < 8; e++) if (rw[e] > rw[i0]) i0 = e;
        int i1 = (i0 == 0) ? 1 : 0;
        #pragma unroll
        for (int e = 0; e < 8; e++) if (e != i0 && rw[e] > rw[i1]) i1 = e;
        float w0 = rw[i0], w1 = rw[i1];
        float d = w0 + w1 + 1e-10f;
        g_tke[2*n]   = i0; g_tke[2*n+1] = i1;
        g_tkw[2*n]   = w0 / d; g_tkw[2*n+1] = w1 / d;
    }
}

// ---------------- stable expert dispatch (single block) ----------------
__global__ __launch_bounds__(256) void route_kernel() {
    __shared__ int cnts[256][8];
    int tid = threadIdx.x;
    int c[8];
    #pragma unroll
    for (int e = 0; e < 8; e++) c[e] = 0;
    int base = tid * 32;
    for (int i = 0; i < 32; i++) c[g_tke[base + i]]++;
    #pragma unroll
    for (int e = 0; e < 8; e++) cnts[tid][e] = c[e];
    __syncthreads();
    if (tid < 8) {
        int run = 0;
        for (int t = 0; t < 256; t++) { int tmp = cnts[t][tid]; cnts[t][tid] = run; run += tmp; }
        g_me[tid] = run < CAP ? run : CAP;
    }
    __syncthreads();
    #pragma unroll
    for (int e = 0; e < 8; e++) c[e] = cnts[tid][e];
    for (int i = 0; i < 32; i++) {
        int gi = base + i;
        int e = g_tke[gi];
        int pos = c[e]++;
        if (pos < CAP) {
            int row = e * CAP + pos;
            g_rowsrc[row]   = gi >> 1;
            g_entryrow[gi]  = row;
        } else {
            g_entryrow[gi] = -1;
        }
    }
}

// ---------------- combine ----------------
__global__ __launch_bounds__(256) void combine_kernel(float* __restrict__ outx) {
    int n = blockIdx.x, tid = threadIdx.x;
    float4 r = ((const float4*)(g_x1 + (long)n*C_))[tid];
    #pragma unroll
    for (int s = 0; s < 2; s++) {
        int row = g_entryrow[n*2 + s];
        if (row >= 0) {
            float ww = g_tkw[n*2 + s];
            float4 bv = ((const float4*)(g_bo + (long)row*C_))[tid];
            r.x = fmaf(ww, bv.x, r.x); r.y = fmaf(ww, bv.y, r.y);
            r.z = fmaf(ww, bv.z, r.z); r.w = fmaf(ww, bv.w, r.w);
        }
    }
    ((float4*)(outx + (long)n*C_))[tid] = r;
}

// ---------------- host launcher ----------------
static inline void do_split(const float* src, void* hi, void* lo, long nelem) {
    int n2 = (int)(nelem >> 1);
    split_kernel<<<(n2 + 255)/256, 256>>>(src, (unsigned*)hi, (unsigned*)lo, n2);
}

extern "C" void kernel_launch(void* const* d_in, const int* in_sizes, int n_in,
                              void* d_out, int out_size) {
    const float* x    = (const float*)d_in[0];
    const float* ve   = (const float*)d_in[1];
    const float* cosb = (const float*)d_in[2];
    const float* sinb = (const float*)d_in[3];
    const float* cqw  = (const float*)d_in[4];
    const float* ckw  = (const float*)d_in[5];
    const float* cvw  = (const float*)d_in[6];
    const float* cpw  = (const float*)d_in[7];
    const float* gw   = (const float*)d_in[8];
    const float* rww  = (const float*)d_in[9];
    const float* fcw  = (const float*)d_in[10];
    const float* pjw  = (const float*)d_in[11];
    const int*   wptr = (const int*)d_in[12];
    float* out = (float*)d_out;

    float *xn, *q, *k, *v, *y, *x1, *xn2, *bo;
    int *rowsrc, *me;
    cudaGetSymbolAddress((void**)&xn,  g_xn);
    cudaGetSymbolAddress((void**)&q,   g_q);
    cudaGetSymbolAddress((void**)&k,   g_k);
    cudaGetSymbolAddress((void**)&v,   g_v);
    cudaGetSymbolAddress((void**)&y,   g_y);
    cudaGetSymbolAddress((void**)&x1,  g_x1);
    cudaGetSymbolAddress((void**)&xn2, g_xn2);
    cudaGetSymbolAddress((void**)&bo,  g_bo);
    cudaGetSymbolAddress((void**)&rowsrc, g_rowsrc);
    cudaGetSymbolAddress((void**)&me,     g_me);

    void *xnh,*xnl, *yh,*yl, *xn2h,*xn2l;
    void *wqh,*wql, *wkh,*wkl, *wvh,*wvl, *wph,*wpl, *wfh,*wfl, *wjh,*wjl, *hh,*hl;
    cudaGetSymbolAddress(&xnh, s_xn_h);   cudaGetSymbolAddress(&xnl, s_xn_l);
    cudaGetSymbolAddress(&yh,  s_y_h);    cudaGetSymbolAddress(&yl,  s_y_l);
    cudaGetSymbolAddress(&xn2h,s_xn2_h);  cudaGetSymbolAddress(&xn2l,s_xn2_l);
    cudaGetSymbolAddress(&wqh, w_q_h);    cudaGetSymbolAddress(&wql, w_q_l);
    cudaGetSymbolAddress(&wkh, w_k_h);    cudaGetSymbolAddress(&wkl, w_k_l);
    cudaGetSymbolAddress(&wvh, w_v_h);    cudaGetSymbolAddress(&wvl, w_v_l);
    cudaGetSymbolAddress(&wph, w_p_h);    cudaGetSymbolAddress(&wpl, w_p_l);
    cudaGetSymbolAddress(&wfh, w_fc_h);   cudaGetSymbolAddress(&wfl, w_fc_l);
    cudaGetSymbolAddress(&wjh, w_pj_h);   cudaGetSymbolAddress(&wjl, w_pj_l);
    cudaGetSymbolAddress(&hh,  s_h_h);    cudaGetSymbolAddress(&hl,  s_h_l);

    const int SMEM = 3*32768;  // 96KB
    cudaFuncSetAttribute(gemm_bf, cudaFuncAttributeMaxDynamicSharedMemorySize, SMEM);

    typedef const unsigned short* cus;

    // weight splits (independent of data flow)
    do_split(cqw, wqh, wql, (long)NH*HD*C_);
    do_split(ckw, wkh, wkl, (long)NKV*HD*C_);
    do_split(cvw, wvh, wvl, (long)NKV*HD*C_);
    do_split(cpw, wph, wpl, (long)C_*C_);
    do_split(fcw, wfh, wfl, (long)E_*H_*C_);
    do_split(pjw, wjh, wjl, (long)E_*C_*H_);

    // 1) xn = rms(x); split
    rms_kernel<<<NTOK, 256>>>(x, xn);
    do_split(xn, xnh, xnl, (long)NTOK*C_);

    // 2) q/k/v projections
    gemm_bf<<<dim3(NH*HD/128,  NTOK/128, 1), 256, SMEM>>>(
        (cus)xnh, (cus)xnl, 0, (cus)wqh, (cus)wql, 0,
        q, nullptr, nullptr, 0, nullptr, NTOK, NH*HD, C_, nullptr, nullptr, 0);
    gemm_bf<<<dim3(NKV*HD/128, NTOK/128, 1), 256, SMEM>>>(
        (cus)xnh, (cus)xnl, 0, (cus)wkh, (cus)wkl, 0,
        k, nullptr, nullptr, 0, nullptr, NTOK, NKV*HD, C_, nullptr, nullptr, 0);
    gemm_bf<<<dim3(NKV*HD/128, NTOK/128, 1), 256, SMEM>>>(
        (cus)xnh, (cus)xnl, 0, (cus)wvh, (cus)wvl, 0,
        v, nullptr, nullptr, 0, nullptr, NTOK, NKV*HD, C_, nullptr, nullptr, 0);

    // 3) gate + v update + rope + q/k rms
    gate_rope_kernel<<<NTOK, 256>>>(ve, cosb, sinb, gw);
    // 4) attention
    attn_kernel<<<dim3(T_/128, NH, B_), 128>>>(wptr);
    // 5) x1 = x + y @ c_proj^T
    do_split(y, yh, yl, (long)NTOK*C_);
    gemm_bf<<<dim3(C_/128, NTOK/128, 1), 256, SMEM>>>(
        (cus)yh, (cus)yl, 0, (cus)wph, (cus)wpl, 0,
        x1, nullptr, nullptr, 0, x, NTOK, C_, C_, nullptr, nullptr, 1);
    // 6) xn2 = rms(x1); split
    rms_kernel<<<NTOK, 256>>>(x1, xn2);
    do_split(xn2, xn2h, xn2l, (long)NTOK*C_);
    // 7) router softmax + top-2 (fp32 exact; writes rw output region)
    router_kernel<<<NTOK, 256>>>(rww, out + (long)NTOK * C_);
    // 8) stable dispatch
    route_kernel<<<1, 256>>>();
    // 9) h = relu(xn2[gather] @ fc_w[e]^T)^2  -> split bf16 out
    gemm_bf<<<dim3(H_/128, CAP/128, E_), 256, SMEM>>>(
        (cus)xn2h, (cus)xn2l, 0, (cus)wfh, (cus)wfl, (long)H_*C_,
        nullptr, (unsigned*)hh, (unsigned*)hl, (long)CAP*H_, nullptr,
        CAP, H_, C_, rowsrc, me, 2);
    // 10) bo = h @ proj_w[e]^T
    gemm_bf<<<dim3(C_/128, CAP/128, E_), 256, SMEM>>>(
        (cus)hh, (cus)hl, (long)CAP*H_, (cus)wjh, (cus)wjl, (long)C_*H_,
        bo, nullptr, nullptr, (long)CAP*C_, nullptr,
        CAP, C_, H_, nullptr, me, 0);
    // 11) final combine -> x output region
    combine_kernel<<<NTOK, 256>>>(out);
}